// round 12
// baseline (speedup 1.0000x reference)
#include <cuda_runtime.h>
#include <cuda_bf16.h>

// StixelLoss v12: R11 engine + cp.async.bulk.prefetch.L2 pacing stream.
// inputs:  (B=256, C=2, H=192, W=256) f32 in (1e-4, 1-1e-4)
// targets: (1, B, C, H, W) f32
// out:     scalar f32 = 1.0*bce_mean + 0.001*cuts + 0.1*dense

#define HH    192
#define WW    256
#define NBC   512
#define NBLK  (NBC * 2)       // 1024 blocks: (b, c, w-half)
#define WH    128             // columns per block
#define NQ    32              // float4 quads per block row
#define NSEG  8               // 24-row segments
#define SEGH  24
#define TABN  1216            // 1/d^3 lookup incl. sentinel fold
#define SENT  (-1000)         // prev sentinel: pos-SENT in [1001,1190] -> tab 0
#define PD    4               // prefetch distance in rows (within segment walk)

__device__ float    g_acc = 0.0f;
__device__ unsigned g_cnt = 0u;

__device__ __forceinline__ void l2_prefetch_512(const void* p) {
    asm volatile("cp.async.bulk.prefetch.L2.global [%0], 512;"
                 :: "l"(p) : "memory");
}

__global__ __launch_bounds__(256, 8)
void stixel_kernel(const float* __restrict__ inp,
                   const float* __restrict__ tgt,
                   float* __restrict__ out) {
    const int bc = blockIdx.x >> 1;          // b*2 + c
    const int wh = blockIdx.x & 1;           // w-half
    const int c  = bc & 1;
    const int q  = threadIdx.x & (NQ - 1);   // quad (cols 4q..4q+3 in half)
    const int s  = threadIdx.x >> 5;         // h-segment 0..7
    const int h0 = s * SEGH;

    __shared__ float        tab[TABN];
    __shared__ unsigned int smask[NSEG][WH];
    __shared__ float        sred[8];

    // channel-1 blocks: fill 1/d^3 table (zero outside [1,190])
    if (c == 1) {
        for (int k = threadIdx.x; k < TABN; k += 256) {
            float fd = (float)k;
            tab[k] = (k >= 1 && k < HH - 1) ? (1.0f / (fd * fd * fd)) : 0.0f;
        }
    }

    // block-level row base (column offset of this w-half), for prefetch
    const float* gp_blk = inp + (size_t)bc * (HH * WW) + (size_t)wh * WH;
    const float* gt_blk = tgt + (size_t)bc * (HH * WW) + (size_t)wh * WH;

    const size_t base = (size_t)bc * (HH * WW) + (size_t)h0 * WW
                      + (size_t)wh * WH + 4 * q;
    const float4* ip4 = (const float4*)(inp + base);
    const float4* tp4 = (const float4*)(tgt + base);

    float bce = 0.0f;
    unsigned int m0 = 0, m1 = 0, m2 = 0, m3 = 0;

    const bool pf_lane = ((threadIdx.x & 31) == 0);

    // hot loop (identical both channels): log2-domain BCE + mask build.
    // lane 0 of each warp keeps an L2 prefetch stream PD rows ahead of its
    // segment, pacing DRAM independently of warp scoreboard stalls.
    #pragma unroll
    for (int i = 0; i < SEGH; ++i) {
        if (pf_lane) {
            const int hp = h0 + i + PD;
            if (hp < HH) {
                l2_prefetch_512(gp_blk + (size_t)hp * WW);
                l2_prefetch_512(gt_blk + (size_t)hp * WW);
            }
        }
        float4 p = __ldcg(ip4 + i * (WW / 4));
        float4 t = __ldcg(tp4 + i * (WW / 4));
        {
            float lp = __log2f(p.x), l1p = __log2f(1.0f - p.x);
            bce += l1p + t.x * (lp - l1p);
            if (p.x > 0.5f) m0 |= (1u << i);
        }
        {
            float lp = __log2f(p.y), l1p = __log2f(1.0f - p.y);
            bce += l1p + t.y * (lp - l1p);
            if (p.y > 0.5f) m1 |= (1u << i);
        }
        {
            float lp = __log2f(p.z), l1p = __log2f(1.0f - p.z);
            bce += l1p + t.z * (lp - l1p);
            if (p.z > 0.5f) m2 |= (1u << i);
        }
        {
            float lp = __log2f(p.w), l1p = __log2f(1.0f - p.w);
            bce += l1p + t.w * (lp - l1p);
            if (p.w > 0.5f) m3 |= (1u << i);
        }
    }

    float dense = 0.0f;
    int   cuts  = 0;

    if (c == 0) {
        cuts = __popc(m0) + __popc(m1) + __popc(m2) + __popc(m3);
    } else {
        smask[s][4 * q + 0] = m0;
        smask[s][4 * q + 1] = m1;
        smask[s][4 * q + 2] = m2;
        smask[s][4 * q + 3] = m3;
        __syncthreads();

        const int col  = threadIdx.x & (WH - 1);
        const int half = threadIdx.x >> 7;   // 0: rows 0..95, 1: rows 96..191

        int prev = SENT;
        if (half == 1) {
            // initial prev = last hit in rows 0..95 (bit 0 of seg0 invisible)
            unsigned int u3 = smask[3][col];
            unsigned int u2 = smask[2][col];
            unsigned int u1 = smask[1][col];
            unsigned int u0 = smask[0][col] & ~1u;
            if      (u3) prev = 72 + 31 - __clz(u3);
            else if (u2) prev = 48 + 31 - __clz(u2);
            else if (u1) prev = 24 + 31 - __clz(u1);
            else if (u0) prev =      31 - __clz(u0);
        }

        #pragma unroll
        for (int k = 0; k < 4; ++k) {
            unsigned int w = smask[half * 4 + k][col];
            if (half == 0 && k == 0) w &= ~1u;          // h=0 hit invisible
            if (half == 1 && k == 3) w &= ~(1u << 23);  // h=191 excluded
            const int rowbase = (half * 4 + k) * SEGH;
            while (w) {
                int b = __ffs(w) - 1;
                w &= (w - 1);
                int pos = rowbase + b;
                dense += tab[pos - prev];   // tab==0 when prev is sentinel
                prev = pos;
            }
        }
    }

    // combine (ALPHA=1, BETA=0.001, GAMMA=0.1); bce is in log2 units
    const float SCALE_BCE = -0.69314718055994531f /
                            (float)((size_t)NBC * HH * WW);
    float val = bce * SCALE_BCE + 0.001f * (float)cuts + 0.1f * dense;

    // block reduction over 256 threads
    #pragma unroll
    for (int off = 16; off > 0; off >>= 1)
        val += __shfl_down_sync(0xffffffffu, val, off);
    const int lane = threadIdx.x & 31;
    const int wid  = threadIdx.x >> 5;
    if (lane == 0) sred[wid] = val;
    __syncthreads();

    if (wid == 0) {
        val = (lane < 8) ? sred[lane] : 0.0f;
        #pragma unroll
        for (int off = 4; off > 0; off >>= 1)
            val += __shfl_down_sync(0xffffffffu, val, off);
        if (lane == 0) {
            atomicAdd(&g_acc, val);
            __threadfence();
            unsigned old = atomicAdd(&g_cnt, 1u);
            if (old == NBLK - 1) {
                // last block: publish result, reset scratch for next replay
                float total = atomicAdd(&g_acc, 0.0f);  // coherent read
                out[0] = total;
                __threadfence();
                g_acc = 0.0f;
                g_cnt = 0u;
            }
        }
    }
}

extern "C" void kernel_launch(void* const* d_in, const int* in_sizes, int n_in,
                              void* d_out, int out_size) {
    const float* inp = (const float*)d_in[0];
    const float* tgt = (const float*)d_in[1];
    float* out = (float*)d_out;

    stixel_kernel<<<NBLK, 256>>>(inp, tgt, out);
}

// round 13
// speedup vs baseline: 1.0892x; 1.0892x over previous
#include <cuda_runtime.h>
#include <cuda_bf16.h>

// StixelLoss v13: R11 engine + L2::256B promotion on the hot loads.
// inputs:  (B=256, C=2, H=192, W=256) f32 in (1e-4, 1-1e-4)
// targets: (1, B, C, H, W) f32
// out:     scalar f32 = 1.0*bce_mean + 0.001*cuts + 0.1*dense

#define HH    192
#define WW    256
#define NBC   512
#define NBLK  (NBC * 2)       // 1024 blocks: (b, c, w-half)
#define WH    128             // columns per block
#define NQ    32              // float4 quads per block row
#define NSEG  8               // 24-row segments
#define SEGH  24
#define TABN  1216            // 1/d^3 lookup incl. sentinel fold
#define SENT  (-1000)         // prev sentinel: pos-SENT in [1001,1190] -> tab 0

__device__ float    g_acc = 0.0f;
__device__ unsigned g_cnt = 0u;

// L1-bypassing load with 256B L2 promotion: each L2 miss pulls a 256B
// granule (dense access -> every byte consumed), halving DRAM request count.
__device__ __forceinline__ float4 ldcg_256(const float4* p) {
    float4 v;
    asm volatile("ld.global.cg.L2::256B.v4.f32 {%0,%1,%2,%3}, [%4];"
                 : "=f"(v.x), "=f"(v.y), "=f"(v.z), "=f"(v.w)
                 : "l"(p));
    return v;
}

__global__ __launch_bounds__(256, 8)
void stixel_kernel(const float* __restrict__ inp,
                   const float* __restrict__ tgt,
                   float* __restrict__ out) {
    const int bc = blockIdx.x >> 1;          // b*2 + c
    const int wh = blockIdx.x & 1;           // w-half
    const int c  = bc & 1;
    const int q  = threadIdx.x & (NQ - 1);   // quad (cols 4q..4q+3 in half)
    const int s  = threadIdx.x >> 5;         // h-segment 0..7
    const int h0 = s * SEGH;

    __shared__ float        tab[TABN];
    __shared__ unsigned int smask[NSEG][WH];
    __shared__ float        sred[8];

    // channel-1 blocks: fill 1/d^3 table (zero outside [1,190])
    if (c == 1) {
        for (int k = threadIdx.x; k < TABN; k += 256) {
            float fd = (float)k;
            tab[k] = (k >= 1 && k < HH - 1) ? (1.0f / (fd * fd * fd)) : 0.0f;
        }
    }

    const size_t base = (size_t)bc * (HH * WW) + (size_t)h0 * WW
                      + (size_t)wh * WH + 4 * q;
    const float4* ip4 = (const float4*)(inp + base);
    const float4* tp4 = (const float4*)(tgt + base);

    float bce = 0.0f;
    unsigned int m0 = 0, m1 = 0, m2 = 0, m3 = 0;

    // hot loop (identical both channels): log2-domain BCE + mask build
    #pragma unroll
    for (int i = 0; i < SEGH; ++i) {
        float4 p = ldcg_256(ip4 + i * (WW / 4));
        float4 t = ldcg_256(tp4 + i * (WW / 4));
        {
            float lp = __log2f(p.x), l1p = __log2f(1.0f - p.x);
            bce += l1p + t.x * (lp - l1p);
            if (p.x > 0.5f) m0 |= (1u << i);
        }
        {
            float lp = __log2f(p.y), l1p = __log2f(1.0f - p.y);
            bce += l1p + t.y * (lp - l1p);
            if (p.y > 0.5f) m1 |= (1u << i);
        }
        {
            float lp = __log2f(p.z), l1p = __log2f(1.0f - p.z);
            bce += l1p + t.z * (lp - l1p);
            if (p.z > 0.5f) m2 |= (1u << i);
        }
        {
            float lp = __log2f(p.w), l1p = __log2f(1.0f - p.w);
            bce += l1p + t.w * (lp - l1p);
            if (p.w > 0.5f) m3 |= (1u << i);
        }
    }

    float dense = 0.0f;
    int   cuts  = 0;

    if (c == 0) {
        cuts = __popc(m0) + __popc(m1) + __popc(m2) + __popc(m3);
    } else {
        smask[s][4 * q + 0] = m0;
        smask[s][4 * q + 1] = m1;
        smask[s][4 * q + 2] = m2;
        smask[s][4 * q + 3] = m3;
        __syncthreads();

        const int col  = threadIdx.x & (WH - 1);
        const int half = threadIdx.x >> 7;   // 0: rows 0..95, 1: rows 96..191

        int prev = SENT;
        if (half == 1) {
            // initial prev = last hit in rows 0..95 (bit 0 of seg0 invisible)
            unsigned int u3 = smask[3][col];
            unsigned int u2 = smask[2][col];
            unsigned int u1 = smask[1][col];
            unsigned int u0 = smask[0][col] & ~1u;
            if      (u3) prev = 72 + 31 - __clz(u3);
            else if (u2) prev = 48 + 31 - __clz(u2);
            else if (u1) prev = 24 + 31 - __clz(u1);
            else if (u0) prev =      31 - __clz(u0);
        }

        #pragma unroll
        for (int k = 0; k < 4; ++k) {
            unsigned int w = smask[half * 4 + k][col];
            if (half == 0 && k == 0) w &= ~1u;          // h=0 hit invisible
            if (half == 1 && k == 3) w &= ~(1u << 23);  // h=191 excluded
            const int rowbase = (half * 4 + k) * SEGH;
            while (w) {
                int b = __ffs(w) - 1;
                w &= (w - 1);
                int pos = rowbase + b;
                dense += tab[pos - prev];   // tab==0 when prev is sentinel
                prev = pos;
            }
        }
    }

    // combine (ALPHA=1, BETA=0.001, GAMMA=0.1); bce is in log2 units
    const float SCALE_BCE = -0.69314718055994531f /
                            (float)((size_t)NBC * HH * WW);
    float val = bce * SCALE_BCE + 0.001f * (float)cuts + 0.1f * dense;

    // block reduction over 256 threads
    #pragma unroll
    for (int off = 16; off > 0; off >>= 1)
        val += __shfl_down_sync(0xffffffffu, val, off);
    const int lane = threadIdx.x & 31;
    const int wid  = threadIdx.x >> 5;
    if (lane == 0) sred[wid] = val;
    __syncthreads();

    if (wid == 0) {
        val = (lane < 8) ? sred[lane] : 0.0f;
        #pragma unroll
        for (int off = 4; off > 0; off >>= 1)
            val += __shfl_down_sync(0xffffffffu, val, off);
        if (lane == 0) {
            atomicAdd(&g_acc, val);
            __threadfence();
            unsigned old = atomicAdd(&g_cnt, 1u);
            if (old == NBLK - 1) {
                // last block: publish result, reset scratch for next replay
                float total = atomicAdd(&g_acc, 0.0f);  // coherent read
                out[0] = total;
                __threadfence();
                g_acc = 0.0f;
                g_cnt = 0u;
            }
        }
    }
}

extern "C" void kernel_launch(void* const* d_in, const int* in_sizes, int n_in,
                              void* d_out, int out_size) {
    const float* inp = (const float*)d_in[0];
    const float* tgt = (const float*)d_in[1];
    float* out = (float*)d_out;

    stixel_kernel<<<NBLK, 256>>>(inp, tgt, out);
}